// round 1
// baseline (speedup 1.0000x reference)
#include <cuda_runtime.h>
#include <math.h>

// Problem constants
constexpr int B_   = 4;
constexpr int L_   = 2048;
constexpr int DM   = 1024;   // d_model
constexpr int H_   = 16;     // heads
constexpr int DK   = 64;     // head dim
constexpr int MR   = B_ * L_;      // 8192 rows
constexpr int QKVN = 3 * DM;       // 3072

// Scratch (device globals: no allocations allowed)
__device__ float g_ln [(size_t)MR * DM];     //  32 MB
__device__ float g_qkv[(size_t)MR * QKVN];   // 100 MB
__device__ float g_att[(size_t)MR * DM];     //  32 MB

// ---------------------------------------------------------------------------
// 1) LayerNorm: one block per row of 1024, 256 threads, float4 per thread
// ---------------------------------------------------------------------------
__global__ __launch_bounds__(256) void ln_kernel(const float* __restrict__ x) {
    const int row = blockIdx.x;
    const int tid = threadIdx.x;
    const float4* xr = (const float4*)(x + (size_t)row * DM);
    float4 v = xr[tid];
    float s  = v.x + v.y + v.z + v.w;
    float ss = v.x*v.x + v.y*v.y + v.z*v.z + v.w*v.w;
    #pragma unroll
    for (int o = 16; o > 0; o >>= 1) {
        s  += __shfl_xor_sync(0xffffffffu, s,  o);
        ss += __shfl_xor_sync(0xffffffffu, ss, o);
    }
    __shared__ float sh[2][8];
    if ((tid & 31) == 0) { sh[0][tid >> 5] = s; sh[1][tid >> 5] = ss; }
    __syncthreads();
    float tot = 0.f, tot2 = 0.f;
    #pragma unroll
    for (int i = 0; i < 8; i++) { tot += sh[0][i]; tot2 += sh[1][i]; }
    const float mu  = tot * (1.0f / DM);
    const float var = tot2 * (1.0f / DM) - mu * mu;
    const float rs  = rsqrtf(var + 1e-8f);
    float4 o;
    o.x = (v.x - mu) * rs; o.y = (v.y - mu) * rs;
    o.z = (v.z - mu) * rs; o.w = (v.w - mu) * rs;
    ((float4*)(g_ln + (size_t)row * DM))[tid] = o;
}

// ---------------------------------------------------------------------------
// 2) SGEMM: C[M,N] = A[M,K] @ W[N,K]^T     (both operands K-major)
//    128x128 block tile, 8x8 per thread, K-step 8, 256 threads
// ---------------------------------------------------------------------------
template <int Mdim, int Ndim, int Kdim>
__device__ __forceinline__ void gemm_body(const float* __restrict__ A,
                                          const float* __restrict__ W,
                                          float* __restrict__ C) {
    __shared__ float As[8][128];
    __shared__ float Bs[8][128];
    const int tid  = threadIdx.x;
    const int tx   = tid & 15;
    const int ty   = tid >> 4;
    const int m0   = blockIdx.y * 128;
    const int n0   = blockIdx.x * 128;
    const int lrow = tid >> 1;
    const int lk   = (tid & 1) * 4;

    float acc[8][8];
    #pragma unroll
    for (int i = 0; i < 8; i++)
        #pragma unroll
        for (int j = 0; j < 8; j++) acc[i][j] = 0.f;

    const float* Aptr = A + (size_t)(m0 + lrow) * Kdim + lk;
    const float* Wptr = W + (size_t)(n0 + lrow) * Kdim + lk;

    for (int k0 = 0; k0 < Kdim; k0 += 8) {
        float4 av = *(const float4*)(Aptr + k0);
        float4 bv = *(const float4*)(Wptr + k0);
        __syncthreads();
        As[lk+0][lrow] = av.x; As[lk+1][lrow] = av.y;
        As[lk+2][lrow] = av.z; As[lk+3][lrow] = av.w;
        Bs[lk+0][lrow] = bv.x; Bs[lk+1][lrow] = bv.y;
        Bs[lk+2][lrow] = bv.z; Bs[lk+3][lrow] = bv.w;
        __syncthreads();
        #pragma unroll
        for (int kk = 0; kk < 8; kk++) {
            float ar[8], br[8];
            #pragma unroll
            for (int i = 0; i < 8; i++) ar[i] = As[kk][ty * 8 + i];
            #pragma unroll
            for (int j = 0; j < 8; j++) br[j] = Bs[kk][tx * 8 + j];
            #pragma unroll
            for (int i = 0; i < 8; i++)
                #pragma unroll
                for (int j = 0; j < 8; j++) acc[i][j] += ar[i] * br[j];
        }
    }
    #pragma unroll
    for (int i = 0; i < 8; i++) {
        float* crow = C + (size_t)(m0 + ty * 8 + i) * Ndim + n0 + tx * 8;
        *(float4*)(crow)     = make_float4(acc[i][0], acc[i][1], acc[i][2], acc[i][3]);
        *(float4*)(crow + 4) = make_float4(acc[i][4], acc[i][5], acc[i][6], acc[i][7]);
    }
}

__global__ __launch_bounds__(256) void gemm_qkv_kernel(const float* __restrict__ W) {
    gemm_body<MR, QKVN, DM>(g_ln, W, g_qkv);
}
__global__ __launch_bounds__(256) void gemm_out_kernel(const float* __restrict__ W,
                                                       float* __restrict__ out) {
    gemm_body<MR, DM, DM>(g_att, W, out);
}

// ---------------------------------------------------------------------------
// 3) RoPE in-place on q and k halves of g_qkv. Double precision angles.
//    One thread per (b, l, h, pair-index i in 0..31)
// ---------------------------------------------------------------------------
__global__ __launch_bounds__(256) void rope_kernel() {
    const int idx = blockIdx.x * 256 + threadIdx.x;   // < B*L*H*32 = 4194304
    const int i = idx & 31;
    const int h = (idx >> 5) & 15;
    const int l = (idx >> 9) & 2047;
    const int b = idx >> 20;
    const double invf = pow(10000.0, -(double)(2 * i) / 64.0);
    double sd, cd;
    sincos((double)l * invf, &sd, &cd);
    const float sn = (float)sd, cs = (float)cd;
    const size_t row = (size_t)(b * L_ + l) * QKVN;
    const int cq = h * DK + 2 * i;
    float* q = g_qkv + row + cq;
    float q1 = q[0], q2 = q[1];
    q[0] = q1 * cs - q2 * sn;
    q[1] = q1 * sn + q2 * cs;
    float* k = g_qkv + row + DM + cq;
    float k1 = k[0], k2 = k[1];
    k[0] = k1 * cs - k2 * sn;
    k[1] = k1 * sn + k2 * cs;
}

// ---------------------------------------------------------------------------
// 4) Causal flash attention, fp32.
//    Block: 128 queries x 1 head, 256 threads (2 threads/query, 32 dims each)
//    K/V tiles of 64 keys in SMEM; online softmax; shfl_xor(1) for dot-sum.
// ---------------------------------------------------------------------------
constexpr int ATN = 64;  // key tile

__global__ __launch_bounds__(256) void attn_kernel() {
    __shared__ float ks[ATN][DK];
    __shared__ float vs[ATN][DK];

    const int bh = blockIdx.y;          // 0..63
    const int b  = bh >> 4;
    const int h  = bh & 15;
    const int q0 = blockIdx.x * 128;
    const int tid  = threadIdx.x;
    const int iq   = tid >> 1;
    const int half = tid & 1;
    const int qrow = q0 + iq;
    const float scale = 0.125f;         // 1/sqrt(64)

    const float* qp = g_qkv + (size_t)(b * L_ + qrow) * QKVN + h * DK + half * 32;
    float qreg[32];
    #pragma unroll
    for (int d4 = 0; d4 < 8; d4++) {
        float4 t = *(const float4*)(qp + 4 * d4);
        qreg[4*d4+0] = t.x * scale; qreg[4*d4+1] = t.y * scale;
        qreg[4*d4+2] = t.z * scale; qreg[4*d4+3] = t.w * scale;
    }

    float o[32];
    #pragma unroll
    for (int d = 0; d < 32; d++) o[d] = 0.f;
    float m = -1e30f, lsum = 0.f;

    const float* kbase = g_qkv + (size_t)(b * L_) * QKVN + DM + h * DK;
    const float* vbase = kbase + DM;
    const int nk = q0 + 128;            // causal: keys [0, q0+128)

    for (int j0 = 0; j0 < nk; j0 += ATN) {
        __syncthreads();
        // cooperative K/V tile load: 64 rows x 16 float4s each
        for (int t = tid; t < ATN * 16; t += 256) {
            const int row = t >> 4;
            const int c4  = t & 15;
            const int goff = (j0 + row) * QKVN + c4 * 4;
            *(float4*)&ks[row][c4 * 4] = *(const float4*)(kbase + goff);
            *(float4*)&vs[row][c4 * 4] = *(const float4*)(vbase + goff);
        }
        __syncthreads();

        for (int jj = 0; jj < ATN; jj++) {
            float s = 0.f;
            const float* kr = &ks[jj][half * 32];
            #pragma unroll
            for (int d4 = 0; d4 < 8; d4++) {
                float4 kv = *(const float4*)(kr + 4 * d4);
                s += qreg[4*d4+0]*kv.x + qreg[4*d4+1]*kv.y
                   + qreg[4*d4+2]*kv.z + qreg[4*d4+3]*kv.w;
            }
            s += __shfl_xor_sync(0xffffffffu, s, 1);   // full 64-dim dot (pair)
            if (j0 + jj <= qrow) {
                const float mnew = fmaxf(m, s);
                const float p = __expf(s - mnew);
                if (mnew > m) {
                    const float corr = __expf(m - mnew);
                    lsum *= corr;
                    #pragma unroll
                    for (int d = 0; d < 32; d++) o[d] *= corr;
                    m = mnew;
                }
                lsum += p;
                const float* vr = &vs[jj][half * 32];
                #pragma unroll
                for (int d4 = 0; d4 < 8; d4++) {
                    float4 vv = *(const float4*)(vr + 4 * d4);
                    o[4*d4+0] += p * vv.x; o[4*d4+1] += p * vv.y;
                    o[4*d4+2] += p * vv.z; o[4*d4+3] += p * vv.w;
                }
            }
        }
    }

    const float inv = 1.0f / lsum;
    float4* op = (float4*)(g_att + (size_t)(b * L_ + qrow) * DM + h * DK + half * 32);
    #pragma unroll
    for (int d4 = 0; d4 < 8; d4++)
        op[d4] = make_float4(o[4*d4+0]*inv, o[4*d4+1]*inv, o[4*d4+2]*inv, o[4*d4+3]*inv);
}

// ---------------------------------------------------------------------------
// launch
// ---------------------------------------------------------------------------
extern "C" void kernel_launch(void* const* d_in, const int* in_sizes, int n_in,
                              void* d_out, int out_size) {
    const float* x    = (const float*)d_in[0];
    const float* W_in = (const float*)d_in[1];
    const float* W_o  = (const float*)d_in[2];
    float* out = (float*)d_out;

    ln_kernel<<<MR, 256>>>(x);

    dim3 g1(QKVN / 128, MR / 128);
    gemm_qkv_kernel<<<g1, 256>>>(W_in);

    rope_kernel<<<(B_ * L_ * H_ * 32) / 256, 256>>>();

    dim3 ga(L_ / 128, B_ * H_);
    attn_kernel<<<ga, 256>>>();

    dim3 g2(DM / 128, MR / 128);
    gemm_out_kernel<<<g2, 256>>>(W_o, out);
}

// round 11
// speedup vs baseline: 1.9172x; 1.9172x over previous
#include <cuda_runtime.h>
#include <cuda_bf16.h>
#include <cstdint>
#include <math.h>

// Problem constants
constexpr int B_   = 4;
constexpr int L_   = 2048;
constexpr int DM   = 1024;   // d_model
constexpr int H_   = 16;     // heads
constexpr int DK   = 64;     // head dim
constexpr int MR   = B_ * L_;      // 8192 rows
constexpr int QKVN = 3 * DM;       // 3072

// Scratch (device globals: no allocations allowed)
__device__ float g_ln [(size_t)MR * DM];     //  32 MB
__device__ float g_qkv[(size_t)MR * QKVN];   // 100 MB
__device__ float g_att[(size_t)MR * DM];     //  32 MB
__device__ float g_rope[2][L_][32];          // [cos|sin][l][i]
__device__ int   g_canary;                   // 0 ok / 1 mma-zeros / 2 mma-wrong
__device__ float g_canary_dump[8];           // keep-alive sink (never read by host)

// m16n8k16 bf16 MMA (canary only this round)
__device__ __forceinline__ void mma16816(float* d, const uint32_t* a, const uint32_t* b) {
    asm volatile(
        "mma.sync.aligned.m16n8k16.row.col.f32.bf16.bf16.f32 "
        "{%0,%1,%2,%3}, {%4,%5,%6,%7}, {%8,%9}, {%0,%1,%2,%3};"
        : "+f"(d[0]), "+f"(d[1]), "+f"(d[2]), "+f"(d[3])
        : "r"(a[0]), "r"(a[1]), "r"(a[2]), "r"(a[3]), "r"(b[0]), "r"(b[1]));
}

// ---------------------------------------------------------------------------
// 1) LayerNorm (R1-proven): one block per row of 1024, 256 threads
// ---------------------------------------------------------------------------
__global__ __launch_bounds__(256) void ln_kernel(const float* __restrict__ x) {
    const int row = blockIdx.x;
    const int tid = threadIdx.x;
    const float4* xr = (const float4*)(x + (size_t)row * DM);
    float4 v = xr[tid];
    float s  = v.x + v.y + v.z + v.w;
    float ss = v.x*v.x + v.y*v.y + v.z*v.z + v.w*v.w;
    #pragma unroll
    for (int o = 16; o > 0; o >>= 1) {
        s  += __shfl_xor_sync(0xffffffffu, s,  o);
        ss += __shfl_xor_sync(0xffffffffu, ss, o);
    }
    __shared__ float sh[2][8];
    if ((tid & 31) == 0) { sh[0][tid >> 5] = s; sh[1][tid >> 5] = ss; }
    __syncthreads();
    float tot = 0.f, tot2 = 0.f;
    #pragma unroll
    for (int i = 0; i < 8; i++) { tot += sh[0][i]; tot2 += sh[1][i]; }
    const float mu  = tot * (1.0f / DM);
    const float var = tot2 * (1.0f / DM) - mu * mu;
    const float rs  = rsqrtf(var + 1e-8f);
    float4 o;
    o.x = (v.x - mu) * rs; o.y = (v.y - mu) * rs;
    o.z = (v.z - mu) * rs; o.w = (v.w - mu) * rs;
    ((float4*)(g_ln + (size_t)row * DM))[tid] = o;
}

// ---------------------------------------------------------------------------
// 2) SGEMM (R1-proven): C[M,N] = A[M,K] @ W[N,K]^T
//    128x128 block tile, 8x8 per thread, K-step 8, 256 threads
// ---------------------------------------------------------------------------
template <int Mdim, int Ndim, int Kdim>
__device__ __forceinline__ void gemm_body(const float* __restrict__ A,
                                          const float* __restrict__ W,
                                          float* __restrict__ C) {
    __shared__ float As[8][128];
    __shared__ float Bs[8][128];
    const int tid  = threadIdx.x;
    const int tx   = tid & 15;
    const int ty   = tid >> 4;
    const int m0   = blockIdx.y * 128;
    const int n0   = blockIdx.x * 128;
    const int lrow = tid >> 1;
    const int lk   = (tid & 1) * 4;

    float acc[8][8];
    #pragma unroll
    for (int i = 0; i < 8; i++)
        #pragma unroll
        for (int j = 0; j < 8; j++) acc[i][j] = 0.f;

    const float* Aptr = A + (size_t)(m0 + lrow) * Kdim + lk;
    const float* Wptr = W + (size_t)(n0 + lrow) * Kdim + lk;

    for (int k0 = 0; k0 < Kdim; k0 += 8) {
        float4 av = *(const float4*)(Aptr + k0);
        float4 bv = *(const float4*)(Wptr + k0);
        __syncthreads();
        As[lk+0][lrow] = av.x; As[lk+1][lrow] = av.y;
        As[lk+2][lrow] = av.z; As[lk+3][lrow] = av.w;
        Bs[lk+0][lrow] = bv.x; Bs[lk+1][lrow] = bv.y;
        Bs[lk+2][lrow] = bv.z; Bs[lk+3][lrow] = bv.w;
        __syncthreads();
        #pragma unroll
        for (int kk = 0; kk < 8; kk++) {
            float ar[8], br[8];
            #pragma unroll
            for (int i = 0; i < 8; i++) ar[i] = As[kk][ty * 8 + i];
            #pragma unroll
            for (int j = 0; j < 8; j++) br[j] = Bs[kk][tx * 8 + j];
            #pragma unroll
            for (int i = 0; i < 8; i++)
                #pragma unroll
                for (int j = 0; j < 8; j++) acc[i][j] += ar[i] * br[j];
        }
    }
    #pragma unroll
    for (int i = 0; i < 8; i++) {
        float* crow = C + (size_t)(m0 + ty * 8 + i) * Ndim + n0 + tx * 8;
        *(float4*)(crow)     = make_float4(acc[i][0], acc[i][1], acc[i][2], acc[i][3]);
        *(float4*)(crow + 4) = make_float4(acc[i][4], acc[i][5], acc[i][6], acc[i][7]);
    }
}

__global__ __launch_bounds__(256) void gemm_qkv_kernel(const float* __restrict__ W) {
    gemm_body<MR, QKVN, DM>(g_ln, W, g_qkv);
}
__global__ __launch_bounds__(256) void gemm_out_kernel(const float* __restrict__ W,
                                                       float* __restrict__ out) {
    gemm_body<MR, DM, DM>(g_att, W, out);
}

// ---------------------------------------------------------------------------
// 3) RoPE: fp64 table (65k threads) + fp32 apply
// ---------------------------------------------------------------------------
__global__ __launch_bounds__(256) void rope_tab_kernel() {
    const int idx = blockIdx.x * 256 + threadIdx.x;  // < 65536
    const int l = idx >> 5, i = idx & 31;
    const double invf = pow(10000.0, -(double)(2 * i) / 64.0);
    double sd, cd;
    sincos((double)l * invf, &sd, &cd);
    g_rope[0][l][i] = (float)cd;
    g_rope[1][l][i] = (float)sd;
}

__global__ __launch_bounds__(256) void rope_apply_kernel() {
    const int idx = blockIdx.x * 256 + threadIdx.x;   // < B*L*H*32
    const int i = idx & 31;
    const int h = (idx >> 5) & 15;
    const int l = (idx >> 9) & 2047;
    const int b = idx >> 20;
    const float cs = g_rope[0][l][i];
    const float sn = g_rope[1][l][i];
    const size_t row = (size_t)(b * L_ + l) * QKVN;
    const int cq = h * DK + 2 * i;
    float* q = g_qkv + row + cq;
    float q1 = q[0], q2 = q[1];
    q[0] = q1 * cs - q2 * sn;
    q[1] = q1 * sn + q2 * cs;
    float* k = g_qkv + row + DM + cq;
    float k1 = k[0], k2 = k[1];
    k[0] = k1 * cs - k2 * sn;
    k[1] = k1 * sn + k2 * cs;
}

// ---------------------------------------------------------------------------
// 4) Causal flash attention, fp32. Rebalanced: 4 threads/query x 16 dims,
//    2 queries/thread (halves LDS traffic per FMA vs R1's 2-thr/query).
//    Block = 256 threads = 128 queries of one (b,h); 64-key SMEM tiles.
// ---------------------------------------------------------------------------
__global__ __launch_bounds__(256, 2) void attn_kernel() {
    __shared__ float ks[64][64];
    __shared__ float vs[64][64];

    const int bh = blockIdx.y;
    const int b  = bh >> 4;
    const int h  = bh & 15;
    const int q0 = blockIdx.x * 128;
    const int tid  = threadIdx.x;
    const int d    = tid & 3;           // dim-quarter: owns floats d*16..d*16+15
    const int quad = tid >> 2;          // 0..63
    const int qa = q0 + quad;
    const int qb = q0 + 64 + quad;
    const float scale = 0.125f;         // 1/sqrt(64)

    const float* qpa = g_qkv + (size_t)(b * L_ + qa) * QKVN + h * DK + d * 16;
    const float* qpb = g_qkv + (size_t)(b * L_ + qb) * QKVN + h * DK + d * 16;
    float qra[16], qrb[16];
    #pragma unroll
    for (int c = 0; c < 4; c++) {
        float4 t = *(const float4*)(qpa + c * 4);
        qra[c*4+0] = t.x*scale; qra[c*4+1] = t.y*scale;
        qra[c*4+2] = t.z*scale; qra[c*4+3] = t.w*scale;
        float4 u = *(const float4*)(qpb + c * 4);
        qrb[c*4+0] = u.x*scale; qrb[c*4+1] = u.y*scale;
        qrb[c*4+2] = u.z*scale; qrb[c*4+3] = u.w*scale;
    }

    float oa[16], ob[16];
    #pragma unroll
    for (int i = 0; i < 16; i++) { oa[i] = 0.f; ob[i] = 0.f; }
    float ma = -1e30f, mb = -1e30f, la = 0.f, lb = 0.f;

    const float* kb8 = g_qkv + (size_t)(b * L_) * QKVN + DM + h * DK;
    const float* vb8 = kb8 + DM;

    for (int j0 = 0; j0 < q0 + 128; j0 += 64) {
        __syncthreads();
        for (int t = tid; t < 1024; t += 256) {
            const int r = t >> 4, c4 = t & 15;
            const size_t go = (size_t)(j0 + r) * QKVN + c4 * 4;
            *(float4*)&ks[r][c4 * 4] = *(const float4*)(kb8 + go);
            *(float4*)&vs[r][c4 * 4] = *(const float4*)(vb8 + go);
        }
        __syncthreads();

        for (int jj = 0; jj < 64; jj++) {
            const int j = j0 + jj;
            float sa = 0.f, sbv = 0.f;
            float4 kv[4];
            #pragma unroll
            for (int c = 0; c < 4; c++) kv[c] = *(const float4*)&ks[jj][d * 16 + c * 4];
            #pragma unroll
            for (int c = 0; c < 4; c++) {
                sa  += qra[c*4+0]*kv[c].x + qra[c*4+1]*kv[c].y
                     + qra[c*4+2]*kv[c].z + qra[c*4+3]*kv[c].w;
                sbv += qrb[c*4+0]*kv[c].x + qrb[c*4+1]*kv[c].y
                     + qrb[c*4+2]*kv[c].z + qrb[c*4+3]*kv[c].w;
            }
            // combine the 4 dim-quarters (partners differ only in d = lane&3)
            sa  += __shfl_xor_sync(0xffffffffu, sa, 1);
            sa  += __shfl_xor_sync(0xffffffffu, sa, 2);
            sbv += __shfl_xor_sync(0xffffffffu, sbv, 1);
            sbv += __shfl_xor_sync(0xffffffffu, sbv, 2);

            if (j <= qb) {
                float4 vv[4];
                #pragma unroll
                for (int c = 0; c < 4; c++) vv[c] = *(const float4*)&vs[jj][d * 16 + c * 4];
                {
                    const float mn = fmaxf(mb, sbv);
                    const float p  = __expf(sbv - mn);
                    if (mn > mb) {
                        const float corr = __expf(mb - mn);
                        lb *= corr;
                        #pragma unroll
                        for (int i = 0; i < 16; i++) ob[i] *= corr;
                        mb = mn;
                    }
                    lb += p;
                    #pragma unroll
                    for (int c = 0; c < 4; c++) {
                        ob[c*4+0] += p * vv[c].x; ob[c*4+1] += p * vv[c].y;
                        ob[c*4+2] += p * vv[c].z; ob[c*4+3] += p * vv[c].w;
                    }
                }
                if (j <= qa) {
                    const float mn = fmaxf(ma, sa);
                    const float p  = __expf(sa - mn);
                    if (mn > ma) {
                        const float corr = __expf(ma - mn);
                        la *= corr;
                        #pragma unroll
                        for (int i = 0; i < 16; i++) oa[i] *= corr;
                        ma = mn;
                    }
                    la += p;
                    #pragma unroll
                    for (int c = 0; c < 4; c++) {
                        oa[c*4+0] += p * vv[c].x; oa[c*4+1] += p * vv[c].y;
                        oa[c*4+2] += p * vv[c].z; oa[c*4+3] += p * vv[c].w;
                    }
                }
            }
        }
    }

    const float inva = 1.0f / la;
    const float invb = 1.0f / lb;
    float* opa = g_att + (size_t)(b * L_ + qa) * DM + h * DK + d * 16;
    float* opb = g_att + (size_t)(b * L_ + qb) * DM + h * DK + d * 16;
    #pragma unroll
    for (int c = 0; c < 4; c++) {
        *(float4*)(opa + c * 4) = make_float4(oa[c*4+0]*inva, oa[c*4+1]*inva,
                                              oa[c*4+2]*inva, oa[c*4+3]*inva);
        *(float4*)(opb + c * 4) = make_float4(ob[c*4+0]*invb, ob[c*4+1]*invb,
                                              ob[c*4+2]*invb, ob[c*4+3]*invb);
    }
}

// ---------------------------------------------------------------------------
// 5) HMMA canary: one warp runs one m16n8k16 bf16 MMA on known integer tiles
//    and checks it against an in-kernel scalar reference. Result code goes to
//    g_canary; a tail kernel converts the code into a ~code*2ms spin, visible
//    in next round's dur_us / ncu without affecting correctness.
// ---------------------------------------------------------------------------
__global__ void canary_kernel() {
    __shared__ __nv_bfloat16 As[16][24];
    __shared__ __nv_bfloat16 Bs[8][24];
    const int lane = threadIdx.x;
    if (lane < 16)
        for (int k = 0; k < 16; k++)
            As[lane][k] = __float2bfloat16((float)(((lane * 3 + k) % 7) - 3));
    if (lane < 8)
        for (int k = 0; k < 16; k++)
            Bs[lane][k] = __float2bfloat16((float)(((lane + 2 * k) % 5) - 2));
    __syncwarp();

    const int g   = lane >> 2;
    const int tig = lane & 3;
    uint32_t ra[4], rb[2];
    ra[0] = *(const uint32_t*)&As[g][tig * 2];
    ra[1] = *(const uint32_t*)&As[g + 8][tig * 2];
    ra[2] = *(const uint32_t*)&As[g][tig * 2 + 8];
    ra[3] = *(const uint32_t*)&As[g + 8][tig * 2 + 8];
    rb[0] = *(const uint32_t*)&Bs[g][tig * 2];
    rb[1] = *(const uint32_t*)&Bs[g][tig * 2 + 8];
    float acc[4] = {0.f, 0.f, 0.f, 0.f};
    mma16816(acc, ra, rb);

    // scalar reference for this thread's C elements:
    // c0=C[g][2tig] c1=C[g][2tig+1] c2=C[g+8][2tig] c3=C[g+8][2tig+1]
    float ref[4] = {0.f, 0.f, 0.f, 0.f};
    for (int k = 0; k < 16; k++) {
        const float b0 = __bfloat162float(Bs[tig * 2][k]);
        const float b1 = __bfloat162float(Bs[tig * 2 + 1][k]);
        const float a0 = __bfloat162float(As[g][k]);
        const float a1 = __bfloat162float(As[g + 8][k]);
        ref[0] += a0 * b0; ref[1] += a0 * b1;
        ref[2] += a1 * b0; ref[3] += a1 * b1;
    }
    float maxerr = 0.f, maxabs = 0.f;
    #pragma unroll
    for (int i = 0; i < 4; i++) {
        maxerr = fmaxf(maxerr, fabsf(acc[i] - ref[i]));
        maxabs = fmaxf(maxabs, fabsf(acc[i]));
    }
    #pragma unroll
    for (int o = 16; o > 0; o >>= 1) {
        maxerr = fmaxf(maxerr, __shfl_xor_sync(0xffffffffu, maxerr, o));
        maxabs = fmaxf(maxabs, __shfl_xor_sync(0xffffffffu, maxabs, o));
    }
    if (lane == 0) {
        g_canary = (maxerr < 0.01f) ? 0 : ((maxabs == 0.f) ? 1 : 2);
        g_canary_dump[0] = acc[0];
        g_canary_dump[1] = ref[0];
        g_canary_dump[2] = maxerr;
        g_canary_dump[3] = maxabs;
    }
}

__global__ void delay_kernel() {
    const int code = g_canary;                 // 0 / 1 / 2
    const long long target = (long long)code * 4000000LL;   // ~2ms per code @2GHz
    const long long start = clock64();
    while (clock64() - start < target) {}
    if (code > 100) g_canary_dump[4] = 1.f;    // keep-alive, never taken
}

// ---------------------------------------------------------------------------
// launch
// ---------------------------------------------------------------------------
extern "C" void kernel_launch(void* const* d_in, const int* in_sizes, int n_in,
                              void* d_out, int out_size) {
    const float* x    = (const float*)d_in[0];
    const float* W_in = (const float*)d_in[1];
    const float* W_o  = (const float*)d_in[2];
    float* out = (float*)d_out;

    canary_kernel<<<1, 32>>>();
    rope_tab_kernel<<<(L_ * 32) / 256, 256>>>();
    ln_kernel<<<MR, 256>>>(x);

    dim3 g1(QKVN / 128, MR / 128);
    gemm_qkv_kernel<<<g1, 256>>>(W_in);

    rope_apply_kernel<<<(B_ * L_ * H_ * 32) / 256, 256>>>();

    dim3 ga(L_ / 128, B_ * H_);
    attn_kernel<<<ga, 256>>>();

    dim3 g2(DM / 128, MR / 128);
    gemm_out_kernel<<<g2, 256>>>(W_o, out);

    delay_kernel<<<1, 1>>>();
}

// round 12
// speedup vs baseline: 1.9896x; 1.0377x over previous
#include <cuda_runtime.h>
#include <cuda_bf16.h>
#include <cstdint>
#include <math.h>

// Problem constants
constexpr int B_   = 4;
constexpr int L_   = 2048;
constexpr int DM   = 1024;   // d_model
constexpr int H_   = 16;     // heads
constexpr int DK   = 64;     // head dim
constexpr int MR   = B_ * L_;      // 8192 rows
constexpr int QKVN = 3 * DM;       // 3072

// ---------------------------------------------------------------------------
// Scratch (device globals: no allocations allowed).
// RULE (learned R7/R10): NEVER pass these as kernel args from host code —
// host-side symbol shadows are not device addresses (and GB300 ATS makes the
// bogus access silently succeed). Only reference them inside device code.
// ---------------------------------------------------------------------------
__device__ float         g_ln  [(size_t)MR * DM];
__device__ float         g_qkv [(size_t)MR * QKVN];
__device__ float         g_att [(size_t)MR * DM];
__device__ __nv_bfloat16 g_aln_hi[(size_t)MR * DM];
__device__ __nv_bfloat16 g_aln_lo[(size_t)MR * DM];
__device__ __nv_bfloat16 g_win_hi[(size_t)QKVN * DM];
__device__ __nv_bfloat16 g_win_lo[(size_t)QKVN * DM];
__device__ __nv_bfloat16 g_wo_hi [(size_t)DM * DM];
__device__ __nv_bfloat16 g_wo_lo [(size_t)DM * DM];
__device__ __nv_bfloat16 g_att_hi[(size_t)MR * DM];
__device__ __nv_bfloat16 g_att_lo[(size_t)MR * DM];
__device__ float         g_rope[2][L_][32];
__device__ int           g_bad0, g_bad1;

// m16n8k16 bf16 MMA (canary-proven correct on this toolchain)
__device__ __forceinline__ void mma16816(float* d, const uint32_t* a, const uint32_t* b) {
    asm volatile(
        "mma.sync.aligned.m16n8k16.row.col.f32.bf16.bf16.f32 "
        "{%0,%1,%2,%3}, {%4,%5,%6,%7}, {%8,%9}, {%0,%1,%2,%3};"
        : "+f"(d[0]), "+f"(d[1]), "+f"(d[2]), "+f"(d[3])
        : "r"(a[0]), "r"(a[1]), "r"(a[2]), "r"(a[3]), "r"(b[0]), "r"(b[1]));
}

__device__ __forceinline__ void split_store(float v, __nv_bfloat16* hi, __nv_bfloat16* lo) {
    __nv_bfloat16 h = __float2bfloat16(v);
    *hi = h;
    *lo = __float2bfloat16(v - __bfloat162float(h));
}

// ---------------------------------------------------------------------------
// 0) flag reset
// ---------------------------------------------------------------------------
__global__ void reset_kernel() { g_bad0 = 0; g_bad1 = 0; }

// ---------------------------------------------------------------------------
// 1) LayerNorm -> g_ln (fp32) + bf16 hi/lo split
// ---------------------------------------------------------------------------
__global__ __launch_bounds__(256) void ln_kernel(const float* __restrict__ x) {
    const int row = blockIdx.x;
    const int tid = threadIdx.x;
    float4 v = ((const float4*)(x + (size_t)row * DM))[tid];
    float s  = v.x + v.y + v.z + v.w;
    float ss = v.x*v.x + v.y*v.y + v.z*v.z + v.w*v.w;
    #pragma unroll
    for (int o = 16; o > 0; o >>= 1) {
        s  += __shfl_xor_sync(0xffffffffu, s,  o);
        ss += __shfl_xor_sync(0xffffffffu, ss, o);
    }
    __shared__ float sh[2][8];
    if ((tid & 31) == 0) { sh[0][tid >> 5] = s; sh[1][tid >> 5] = ss; }
    __syncthreads();
    float tot = 0.f, tot2 = 0.f;
    #pragma unroll
    for (int i = 0; i < 8; i++) { tot += sh[0][i]; tot2 += sh[1][i]; }
    const float mu  = tot * (1.0f / DM);
    const float var = tot2 * (1.0f / DM) - mu * mu;
    const float rs  = rsqrtf(var + 1e-8f);
    float o[4] = {(v.x-mu)*rs, (v.y-mu)*rs, (v.z-mu)*rs, (v.w-mu)*rs};
    const size_t base = (size_t)row * DM + tid * 4;
    *(float4*)(g_ln + base) = make_float4(o[0], o[1], o[2], o[3]);
    ushort4 uh, ul;
    unsigned short* ph = &uh.x;
    unsigned short* pl = &ul.x;
    #pragma unroll
    for (int i = 0; i < 4; i++) {
        __nv_bfloat16 hi = __float2bfloat16(o[i]);
        ph[i] = __bfloat16_as_ushort(hi);
        pl[i] = __bfloat16_as_ushort(__float2bfloat16(o[i] - __bfloat162float(hi)));
    }
    *(ushort4*)(g_aln_hi + base) = uh;
    *(ushort4*)(g_aln_lo + base) = ul;
}

// ---------------------------------------------------------------------------
// 2) Weight splits (globals referenced in device code; only W passed as arg)
// ---------------------------------------------------------------------------
__global__ __launch_bounds__(256) void wsplit_win(const float* __restrict__ W) {
    int i = blockIdx.x * 256 + threadIdx.x;
    if (i < QKVN * DM) split_store(W[i], &g_win_hi[i], &g_win_lo[i]);
}
__global__ __launch_bounds__(256) void wsplit_wo(const float* __restrict__ W) {
    int i = blockIdx.x * 256 + threadIdx.x;
    if (i < DM * DM) split_store(W[i], &g_wo_hi[i], &g_wo_lo[i]);
}

// ---------------------------------------------------------------------------
// 3) HMMA bf16-split GEMM body: C[M,N] = A[M,K] @ W[N,K]^T
//    Sections hi*hi + hi*lo + lo*hi over K' = 3K. 128x128 tile, 8 warps
//    (4m x 2n), warp tile 32x64, padded static smem, 64-elem K chunks.
// ---------------------------------------------------------------------------
template <int Ntot, int Kdim>
__device__ __forceinline__ void gemm_mma_body(const __nv_bfloat16* __restrict__ aHi,
                                              const __nv_bfloat16* __restrict__ aLo,
                                              const __nv_bfloat16* __restrict__ bHi,
                                              const __nv_bfloat16* __restrict__ bLo,
                                              float* __restrict__ C) {
    __shared__ __nv_bfloat16 As[128][72];   // 64 data + 8 pad
    __shared__ __nv_bfloat16 Bs[128][72];
    constexpr int KC = Kdim / 64;
    constexpr int NC = 3 * KC;

    const int tid  = threadIdx.x;
    const int lane = tid & 31;
    const int warp = tid >> 5;
    const int wm   = warp & 3;
    const int wn   = warp >> 2;
    const int m0   = blockIdx.y * 128;
    const int n0   = blockIdx.x * 128;
    const int g    = lane >> 2;
    const int tig  = lane & 3;

    float acc[2][8][4];
    #pragma unroll
    for (int mt = 0; mt < 2; mt++)
        #pragma unroll
        for (int nt = 0; nt < 8; nt++)
            #pragma unroll
            for (int i = 0; i < 4; i++) acc[mt][nt][i] = 0.f;

    const int lrow = tid >> 1;
    const int lcol = (tid & 1) * 32;
    uint4 bufA[4], bufB[4];

    auto ldg = [&](int c) {
        const int sec = c / KC;
        const int k0  = (c % KC) * 64;
        const __nv_bfloat16* as = (sec == 2) ? aLo : aHi;
        const __nv_bfloat16* bs = (sec == 1) ? bLo : bHi;
        const uint4* ga = (const uint4*)(as + (size_t)(m0 + lrow) * Kdim + k0 + lcol);
        const uint4* gb = (const uint4*)(bs + (size_t)(n0 + lrow) * Kdim + k0 + lcol);
        #pragma unroll
        for (int i = 0; i < 4; i++) { bufA[i] = ga[i]; bufB[i] = gb[i]; }
    };

    ldg(0);
    for (int c = 0; c < NC; c++) {
        __syncthreads();
        #pragma unroll
        for (int i = 0; i < 4; i++) {
            *(uint4*)&As[lrow][lcol + i * 8] = bufA[i];
            *(uint4*)&Bs[lrow][lcol + i * 8] = bufB[i];
        }
        __syncthreads();
        if (c + 1 < NC) ldg(c + 1);

        #pragma unroll
        for (int ks = 0; ks < 4; ks++) {
            uint32_t ra[2][4];
            #pragma unroll
            for (int mt = 0; mt < 2; mt++) {
                const int r = wm * 32 + mt * 16 + g;
                ra[mt][0] = *(const uint32_t*)&As[r    ][ks * 16 + tig * 2];
                ra[mt][1] = *(const uint32_t*)&As[r + 8][ks * 16 + tig * 2];
                ra[mt][2] = *(const uint32_t*)&As[r    ][ks * 16 + tig * 2 + 8];
                ra[mt][3] = *(const uint32_t*)&As[r + 8][ks * 16 + tig * 2 + 8];
            }
            #pragma unroll
            for (int nt = 0; nt < 8; nt++) {
                const int rn = wn * 64 + nt * 8 + g;
                uint32_t rb[2];
                rb[0] = *(const uint32_t*)&Bs[rn][ks * 16 + tig * 2];
                rb[1] = *(const uint32_t*)&Bs[rn][ks * 16 + tig * 2 + 8];
                mma16816(acc[0][nt], ra[0], rb);
                mma16816(acc[1][nt], ra[1], rb);
            }
        }
    }

    #pragma unroll
    for (int mt = 0; mt < 2; mt++) {
        const int r = m0 + wm * 32 + mt * 16 + g;
        #pragma unroll
        for (int nt = 0; nt < 8; nt++) {
            const int cc = n0 + wn * 64 + nt * 8 + tig * 2;
            *(float2*)(C + (size_t)r * Ntot + cc)       = make_float2(acc[mt][nt][0], acc[mt][nt][1]);
            *(float2*)(C + (size_t)(r + 8) * Ntot + cc) = make_float2(acc[mt][nt][2], acc[mt][nt][3]);
        }
    }
}

// Wrappers: device-side references to globals (real device addresses)
__global__ __launch_bounds__(256) void gemm_qkv_mma() {
    gemm_mma_body<QKVN, DM>(g_aln_hi, g_aln_lo, g_win_hi, g_win_lo, g_qkv);
}
__global__ __launch_bounds__(256) void gemm_out_mma(float* __restrict__ out) {
    gemm_mma_body<DM, DM>(g_att_hi, g_att_lo, g_wo_hi, g_wo_lo, out);
}

// ---------------------------------------------------------------------------
// 4) Verify (256 scalar samples) + scalar fallback (early-exit when clean)
// ---------------------------------------------------------------------------
__global__ __launch_bounds__(256) void verify_qkv(const float* __restrict__ W) {
    const int t = threadIdx.x;
    const int row = t * 32 + ((t * 7) & 31);
    const int col = (t * 997) % QKVN;
    const float* a = g_ln + (size_t)row * DM;
    const float* w = W + (size_t)col * DM;
    float s = 0.f;
    for (int k = 0; k < DM; k++) s += a[k] * w[k];
    const float c = g_qkv[(size_t)row * QKVN + col];
    if (fabsf(c - s) > 0.03f * (fabsf(s) + 1.0f)) g_bad0 = 1;
}
__global__ __launch_bounds__(256) void verify_out(const float* __restrict__ W,
                                                  const float* __restrict__ out) {
    const int t = threadIdx.x;
    const int row = t * 32 + ((t * 7) & 31);
    const int col = (t * 997) % DM;
    const float* a = g_att + (size_t)row * DM;
    const float* w = W + (size_t)col * DM;
    float s = 0.f;
    for (int k = 0; k < DM; k++) s += a[k] * w[k];
    const float c = out[(size_t)row * DM + col];
    if (fabsf(c - s) > 0.03f * (fabsf(s) + 1.0f)) g_bad1 = 1;
}

// Scalar SGEMM body (R1-proven)
template <int Mdim, int Ndim, int Kdim>
__device__ __forceinline__ void gemm_body(const float* __restrict__ A,
                                          const float* __restrict__ W,
                                          float* __restrict__ C) {
    __shared__ float As[8][128];
    __shared__ float Bs[8][128];
    const int tid  = threadIdx.x;
    const int tx   = tid & 15;
    const int ty   = tid >> 4;
    const int m0   = blockIdx.y * 128;
    const int n0   = blockIdx.x * 128;
    const int lrow = tid >> 1;
    const int lk   = (tid & 1) * 4;

    float acc[8][8];
    #pragma unroll
    for (int i = 0; i < 8; i++)
        #pragma unroll
        for (int j = 0; j < 8; j++) acc[i][j] = 0.f;

    const float* Aptr = A + (size_t)(m0 + lrow) * Kdim + lk;
    const float* Wptr = W + (size_t)(n0 + lrow) * Kdim + lk;

    for (int k0 = 0; k0 < Kdim; k0 += 8) {
        float4 av = *(const float4*)(Aptr + k0);
        float4 bv = *(const float4*)(Wptr + k0);
        __syncthreads();
        As[lk+0][lrow] = av.x; As[lk+1][lrow] = av.y;
        As[lk+2][lrow] = av.z; As[lk+3][lrow] = av.w;
        Bs[lk+0][lrow] = bv.x; Bs[lk+1][lrow] = bv.y;
        Bs[lk+2][lrow] = bv.z; Bs[lk+3][lrow] = bv.w;
        __syncthreads();
        #pragma unroll
        for (int kk = 0; kk < 8; kk++) {
            float ar[8], br[8];
            #pragma unroll
            for (int i = 0; i < 8; i++) ar[i] = As[kk][ty * 8 + i];
            #pragma unroll
            for (int j = 0; j < 8; j++) br[j] = Bs[kk][tx * 8 + j];
            #pragma unroll
            for (int i = 0; i < 8; i++)
                #pragma unroll
                for (int j = 0; j < 8; j++) acc[i][j] += ar[i] * br[j];
        }
    }
    #pragma unroll
    for (int i = 0; i < 8; i++) {
        float* crow = C + (size_t)(m0 + ty * 8 + i) * Ndim + n0 + tx * 8;
        *(float4*)(crow)     = make_float4(acc[i][0], acc[i][1], acc[i][2], acc[i][3]);
        *(float4*)(crow + 4) = make_float4(acc[i][4], acc[i][5], acc[i][6], acc[i][7]);
    }
}

__global__ __launch_bounds__(256) void fallback_qkv(const float* __restrict__ W) {
    __shared__ int flag;
    if (threadIdx.x == 0) flag = g_bad0;
    __syncthreads();
    if (!flag) return;
    gemm_body<MR, QKVN, DM>(g_ln, W, g_qkv);
}
__global__ __launch_bounds__(256) void fallback_out(const float* __restrict__ W,
                                                    float* __restrict__ out) {
    __shared__ int flag;
    if (threadIdx.x == 0) flag = g_bad1;
    __syncthreads();
    if (!flag) return;
    gemm_body<MR, DM, DM>(g_att, W, out);
}

// ---------------------------------------------------------------------------
// 5) RoPE: fp64 table + fp32 apply (R11-proven)
// ---------------------------------------------------------------------------
__global__ __launch_bounds__(256) void rope_tab_kernel() {
    const int idx = blockIdx.x * 256 + threadIdx.x;
    const int l = idx >> 5, i = idx & 31;
    const double invf = pow(10000.0, -(double)(2 * i) / 64.0);
    double sd, cd;
    sincos((double)l * invf, &sd, &cd);
    g_rope[0][l][i] = (float)cd;
    g_rope[1][l][i] = (float)sd;
}

__global__ __launch_bounds__(256) void rope_apply_kernel() {
    const int idx = blockIdx.x * 256 + threadIdx.x;
    const int i = idx & 31;
    const int h = (idx >> 5) & 15;
    const int l = (idx >> 9) & 2047;
    const int b = idx >> 20;
    const float cs = g_rope[0][l][i];
    const float sn = g_rope[1][l][i];
    const size_t row = (size_t)(b * L_ + l) * QKVN;
    const int cq = h * DK + 2 * i;
    float* q = g_qkv + row + cq;
    float q1 = q[0], q2 = q[1];
    q[0] = q1 * cs - q2 * sn;
    q[1] = q1 * sn + q2 * cs;
    float* k = g_qkv + row + DM + cq;
    float k1 = k[0], k2 = k[1];
    k[0] = k1 * cs - k2 * sn;
    k[1] = k1 * sn + k2 * cs;
}

// ---------------------------------------------------------------------------
// 6) Causal flash attention (R11-proven), plus bf16 hi/lo split store
// ---------------------------------------------------------------------------
__global__ __launch_bounds__(256, 2) void attn_kernel() {
    __shared__ float ks[64][64];
    __shared__ float vs[64][64];

    const int bh = blockIdx.y;
    const int b  = bh >> 4;
    const int h  = bh & 15;
    const int q0 = blockIdx.x * 128;
    const int tid  = threadIdx.x;
    const int d    = tid & 3;
    const int quad = tid >> 2;
    const int qa = q0 + quad;
    const int qb = q0 + 64 + quad;
    const float scale = 0.125f;

    const float* qpa = g_qkv + (size_t)(b * L_ + qa) * QKVN + h * DK + d * 16;
    const float* qpb = g_qkv + (size_t)(b * L_ + qb) * QKVN + h * DK + d * 16;
    float qra[16], qrb[16];
    #pragma unroll
    for (int c = 0; c < 4; c++) {
        float4 t = *(const float4*)(qpa + c * 4);
        qra[c*4+0] = t.x*scale; qra[c*4+1] = t.y*scale;
        qra[c*4+2] = t.z*scale; qra[c*4+3] = t.w*scale;
        float4 u = *(const float4*)(qpb + c * 4);
        qrb[c*4+0] = u.x*scale; qrb[c*4+1] = u.y*scale;
        qrb[c*4+2] = u.z*scale; qrb[c*4+3] = u.w*scale;
    }

    float oa[16], ob[16];
    #pragma unroll
    for (int i = 0; i < 16; i++) { oa[i] = 0.f; ob[i] = 0.f; }
    float ma = -1e30f, mb = -1e30f, la = 0.f, lb = 0.f;

    const float* kb8 = g_qkv + (size_t)(b * L_) * QKVN + DM + h * DK;
    const float* vb8 = kb8 + DM;

    for (int j0 = 0; j0 < q0 + 128; j0 += 64) {
        __syncthreads();
        for (int t = tid; t < 1024; t += 256) {
            const int r = t >> 4, c4 = t & 15;
            const size_t go = (size_t)(j0 + r) * QKVN + c4 * 4;
            *(float4*)&ks[r][c4 * 4] = *(const float4*)(kb8 + go);
            *(float4*)&vs[r][c4 * 4] = *(const float4*)(vb8 + go);
        }
        __syncthreads();

        for (int jj = 0; jj < 64; jj++) {
            const int j = j0 + jj;
            float sa = 0.f, sbv = 0.f;
            float4 kv[4];
            #pragma unroll
            for (int c = 0; c < 4; c++) kv[c] = *(const float4*)&ks[jj][d * 16 + c * 4];
            #pragma unroll
            for (int c = 0; c < 4; c++) {
                sa  += qra[c*4+0]*kv[c].x + qra[c*4+1]*kv[c].y
                     + qra[c*4+2]*kv[c].z + qra[c*4+3]*kv[c].w;
                sbv += qrb[c*4+0]*kv[c].x + qrb[c*4+1]*kv[c].y
                     + qrb[c*4+2]*kv[c].z + qrb[c*4+3]*kv[c].w;
            }
            sa  += __shfl_xor_sync(0xffffffffu, sa, 1);
            sa  += __shfl_xor_sync(0xffffffffu, sa, 2);
            sbv += __shfl_xor_sync(0xffffffffu, sbv, 1);
            sbv += __shfl_xor_sync(0xffffffffu, sbv, 2);

            if (j <= qb) {
                float4 vv[4];
                #pragma unroll
                for (int c = 0; c < 4; c++) vv[c] = *(const float4*)&vs[jj][d * 16 + c * 4];
                {
                    const float mn = fmaxf(mb, sbv);
                    const float p  = __expf(sbv - mn);
                    if (mn > mb) {
                        const float corr = __expf(mb - mn);
                        lb *= corr;
                        #pragma unroll
                        for (int i = 0; i < 16; i++) ob[i] *= corr;
                        mb = mn;
                    }
                    lb += p;
                    #pragma unroll
                    for (int c = 0; c < 4; c++) {
                        ob[c*4+0] += p * vv[c].x; ob[c*4+1] += p * vv[c].y;
                        ob[c*4+2] += p * vv[c].z; ob[c*4+3] += p * vv[c].w;
                    }
                }
                if (j <= qa) {
                    const float mn = fmaxf(ma, sa);
                    const float p  = __expf(sa - mn);
                    if (mn > ma) {
                        const float corr = __expf(ma - mn);
                        la *= corr;
                        #pragma unroll
                        for (int i = 0; i < 16; i++) oa[i] *= corr;
                        ma = mn;
                    }
                    la += p;
                    #pragma unroll
                    for (int c = 0; c < 4; c++) {
                        oa[c*4+0] += p * vv[c].x; oa[c*4+1] += p * vv[c].y;
                        oa[c*4+2] += p * vv[c].z; oa[c*4+3] += p * vv[c].w;
                    }
                }
            }
        }
    }

    const float inva = 1.0f / la;
    const float invb = 1.0f / lb;
    const size_t offa = (size_t)(b * L_ + qa) * DM + h * DK + d * 16;
    const size_t offb = (size_t)(b * L_ + qb) * DM + h * DK + d * 16;
    #pragma unroll
    for (int c = 0; c < 4; c++) {
        float va[4], vb4[4];
        #pragma unroll
        for (int e = 0; e < 4; e++) { va[e] = oa[c*4+e] * inva; vb4[e] = ob[c*4+e] * invb; }
        *(float4*)(g_att + offa + c * 4) = make_float4(va[0], va[1], va[2], va[3]);
        *(float4*)(g_att + offb + c * 4) = make_float4(vb4[0], vb4[1], vb4[2], vb4[3]);
        ushort4 uh, ul;
        unsigned short* ph = &uh.x;
        unsigned short* pl = &ul.x;
        #pragma unroll
        for (int e = 0; e < 4; e++) {
            __nv_bfloat16 hi = __float2bfloat16(va[e]);
            ph[e] = __bfloat16_as_ushort(hi);
            pl[e] = __bfloat16_as_ushort(__float2bfloat16(va[e] - __bfloat162float(hi)));
        }
        *(ushort4*)(g_att_hi + offa + c * 4) = uh;
        *(ushort4*)(g_att_lo + offa + c * 4) = ul;
        #pragma unroll
        for (int e = 0; e < 4; e++) {
            __nv_bfloat16 hi = __float2bfloat16(vb4[e]);
            ph[e] = __bfloat16_as_ushort(hi);
            pl[e] = __bfloat16_as_ushort(__float2bfloat16(vb4[e] - __bfloat162float(hi)));
        }
        *(ushort4*)(g_att_hi + offb + c * 4) = uh;
        *(ushort4*)(g_att_lo + offb + c * 4) = ul;
    }
}

// ---------------------------------------------------------------------------
// launch
// ---------------------------------------------------------------------------
extern "C" void kernel_launch(void* const* d_in, const int* in_sizes, int n_in,
                              void* d_out, int out_size) {
    const float* x    = (const float*)d_in[0];
    const float* W_in = (const float*)d_in[1];
    const float* W_o  = (const float*)d_in[2];
    float* out = (float*)d_out;

    reset_kernel<<<1, 1>>>();
    rope_tab_kernel<<<(L_ * 32) / 256, 256>>>();
    ln_kernel<<<MR, 256>>>(x);
    wsplit_win<<<(QKVN * DM + 255) / 256, 256>>>(W_in);
    wsplit_wo<<<(DM * DM + 255) / 256, 256>>>(W_o);

    dim3 g1(QKVN / 128, MR / 128);
    gemm_qkv_mma<<<g1, 256>>>();
    verify_qkv<<<1, 256>>>(W_in);
    fallback_qkv<<<g1, 256>>>(W_in);

    rope_apply_kernel<<<(B_ * L_ * H_ * 32) / 256, 256>>>();

    dim3 ga(L_ / 128, B_ * H_);
    attn_kernel<<<ga, 256>>>();

    dim3 g2(DM / 128, MR / 128);
    gemm_out_mma<<<g2, 256>>>(out);
    verify_out<<<1, 256>>>(W_o, out);
    fallback_out<<<g2, 256>>>(W_o, out);
}

// round 16
// speedup vs baseline: 4.1827x; 2.1023x over previous
#include <cuda_runtime.h>
#include <cuda_bf16.h>
#include <cstdint>
#include <math.h>

// Problem constants
constexpr int B_   = 4;
constexpr int L_   = 2048;
constexpr int DM   = 1024;
constexpr int H_   = 16;
constexpr int DK   = 64;
constexpr int MR   = B_ * L_;      // 8192
constexpr int QKVN = 3 * DM;       // 3072

// ---------------------------------------------------------------------------
// Scratch (device globals). RULE: never pass these as kernel args from host.
// ---------------------------------------------------------------------------
__device__ float         g_ln  [(size_t)MR * DM];
__device__ float         g_qkv [(size_t)MR * QKVN];
__device__ float         g_att [(size_t)MR * DM];
__device__ __nv_bfloat16 g_aln_hi[(size_t)MR * DM];
__device__ __nv_bfloat16 g_aln_lo[(size_t)MR * DM];
__device__ __nv_bfloat16 g_win_hi[(size_t)QKVN * DM];
__device__ __nv_bfloat16 g_win_lo[(size_t)QKVN * DM];
__device__ __nv_bfloat16 g_wo_hi [(size_t)DM * DM];
__device__ __nv_bfloat16 g_wo_lo [(size_t)DM * DM];
__device__ __nv_bfloat16 g_att_hi[(size_t)MR * DM];
__device__ __nv_bfloat16 g_att_lo[(size_t)MR * DM];
__device__ float         g_rope[2][L_][32];
__device__ int           g_bad0, g_bad1, g_bad2;

// HW-validated m16n8k16 bf16 MMA
__device__ __forceinline__ void mma16816(float* d, const uint32_t* a, const uint32_t* b) {
    asm volatile(
        "mma.sync.aligned.m16n8k16.row.col.f32.bf16.bf16.f32 "
        "{%0,%1,%2,%3}, {%4,%5,%6,%7}, {%8,%9}, {%0,%1,%2,%3};"
        : "+f"(d[0]), "+f"(d[1]), "+f"(d[2]), "+f"(d[3])
        : "r"(a[0]), "r"(a[1]), "r"(a[2]), "r"(a[3]), "r"(b[0]), "r"(b[1]));
}

__device__ __forceinline__ unsigned short bfh(float x) {
    return __bfloat16_as_ushort(__float2bfloat16(x));
}
__device__ __forceinline__ float bff(unsigned short u) {
    return __bfloat162float(__ushort_as_bfloat16(u));
}
__device__ __forceinline__ uint32_t pack2u(unsigned short a, unsigned short b) {
    return (uint32_t)a | ((uint32_t)b << 16);
}
__device__ __forceinline__ void split_store(float v, __nv_bfloat16* hi, __nv_bfloat16* lo) {
    __nv_bfloat16 h = __float2bfloat16(v);
    *hi = h;
    *lo = __float2bfloat16(v - __bfloat162float(h));
}

// fast exp2 on fma/alu pipes (x <= 0; exact at 0; ~2e-6 rel err)
__device__ __forceinline__ float exp2p(float x) {
    x = fmaxf(x, -100.0f);
    float t = x + 12582912.0f;                 // round-to-nearest int via bias
    int   n = __float_as_int(t) - 0x4B400000;
    float f = x - (t - 12582912.0f);           // f in [-0.5, 0.5]
    float p = 1.33335581e-3f;
    p = fmaf(p, f, 9.61812911e-3f);
    p = fmaf(p, f, 5.55041087e-2f);
    p = fmaf(p, f, 2.40226507e-1f);
    p = fmaf(p, f, 6.93147181e-1f);
    p = fmaf(p, f, 1.0f);
    return p * __int_as_float((n + 127) << 23);
}
constexpr float LOG2E = 1.44269504f;

// ---------------------------------------------------------------------------
__global__ void reset_kernel() { g_bad0 = 0; g_bad1 = 0; g_bad2 = 0; }

// ---------------------------------------------------------------------------
// LayerNorm -> g_ln fp32 + bf16 hi/lo
// ---------------------------------------------------------------------------
__global__ __launch_bounds__(256) void ln_kernel(const float* __restrict__ x) {
    const int row = blockIdx.x;
    const int tid = threadIdx.x;
    float4 v = ((const float4*)(x + (size_t)row * DM))[tid];
    float s  = v.x + v.y + v.z + v.w;
    float ss = v.x*v.x + v.y*v.y + v.z*v.z + v.w*v.w;
    #pragma unroll
    for (int o = 16; o > 0; o >>= 1) {
        s  += __shfl_xor_sync(0xffffffffu, s,  o);
        ss += __shfl_xor_sync(0xffffffffu, ss, o);
    }
    __shared__ float sh[2][8];
    if ((tid & 31) == 0) { sh[0][tid >> 5] = s; sh[1][tid >> 5] = ss; }
    __syncthreads();
    float tot = 0.f, tot2 = 0.f;
    #pragma unroll
    for (int i = 0; i < 8; i++) { tot += sh[0][i]; tot2 += sh[1][i]; }
    const float mu  = tot * (1.0f / DM);
    const float var = tot2 * (1.0f / DM) - mu * mu;
    const float rs  = rsqrtf(var + 1e-8f);
    float o[4] = {(v.x-mu)*rs, (v.y-mu)*rs, (v.z-mu)*rs, (v.w-mu)*rs};
    const size_t base = (size_t)row * DM + tid * 4;
    *(float4*)(g_ln + base) = make_float4(o[0], o[1], o[2], o[3]);
    ushort4 uh, ul;
    unsigned short* ph = &uh.x;
    unsigned short* pl = &ul.x;
    #pragma unroll
    for (int i = 0; i < 4; i++) {
        __nv_bfloat16 hi = __float2bfloat16(o[i]);
        ph[i] = __bfloat16_as_ushort(hi);
        pl[i] = __bfloat16_as_ushort(__float2bfloat16(o[i] - __bfloat162float(hi)));
    }
    *(ushort4*)(g_aln_hi + base) = uh;
    *(ushort4*)(g_aln_lo + base) = ul;
}

// ---------------------------------------------------------------------------
// Weight splits
// ---------------------------------------------------------------------------
__global__ __launch_bounds__(256) void wsplit_win(const float* __restrict__ W) {
    int i = blockIdx.x * 256 + threadIdx.x;
    if (i < QKVN * DM) split_store(W[i], &g_win_hi[i], &g_win_lo[i]);
}
__global__ __launch_bounds__(256) void wsplit_wo(const float* __restrict__ W) {
    int i = blockIdx.x * 256 + threadIdx.x;
    if (i < DM * DM) split_store(W[i], &g_wo_hi[i], &g_wo_lo[i]);
}

// ---------------------------------------------------------------------------
// HMMA bf16-split GEMM (R12-proven, unchanged)
// ---------------------------------------------------------------------------
template <int Ntot, int Kdim>
__device__ __forceinline__ void gemm_mma_body(const __nv_bfloat16* __restrict__ aHi,
                                              const __nv_bfloat16* __restrict__ aLo,
                                              const __nv_bfloat16* __restrict__ bHi,
                                              const __nv_bfloat16* __restrict__ bLo,
                                              float* __restrict__ C) {
    __shared__ __nv_bfloat16 As[128][72];
    __shared__ __nv_bfloat16 Bs[128][72];
    constexpr int KC = Kdim / 64;
    constexpr int NC = 3 * KC;

    const int tid  = threadIdx.x;
    const int lane = tid & 31;
    const int warp = tid >> 5;
    const int wm   = warp & 3;
    const int wn   = warp >> 2;
    const int m0   = blockIdx.y * 128;
    const int n0   = blockIdx.x * 128;
    const int g    = lane >> 2;
    const int tig  = lane & 3;

    float acc[2][8][4];
    #pragma unroll
    for (int mt = 0; mt < 2; mt++)
        #pragma unroll
        for (int nt = 0; nt < 8; nt++)
            #pragma unroll
            for (int i = 0; i < 4; i++) acc[mt][nt][i] = 0.f;

    const int lrow = tid >> 1;
    const int lcol = (tid & 1) * 32;
    uint4 bufA[4], bufB[4];

    auto ldg = [&](int c) {
        const int sec = c / KC;
        const int k0  = (c % KC) * 64;
        const __nv_bfloat16* as = (sec == 2) ? aLo : aHi;
        const __nv_bfloat16* bs = (sec == 1) ? bLo : bHi;
        const uint4* ga = (const uint4*)(as + (size_t)(m0 + lrow) * Kdim + k0 + lcol);
        const uint4* gb = (const uint4*)(bs + (size_t)(n0 + lrow) * Kdim + k0 + lcol);
        #pragma unroll
        for (int i = 0; i < 4; i++) { bufA[i] = ga[i]; bufB[i] = gb[i]; }
    };

    ldg(0);
    for (int c = 0; c < NC; c++) {
        __syncthreads();
        #pragma unroll
        for (int i = 0; i < 4; i++) {
            *(uint4*)&As[lrow][lcol + i * 8] = bufA[i];
            *(uint4*)&Bs[lrow][lcol + i * 8] = bufB[i];
        }
        __syncthreads();
        if (c + 1 < NC) ldg(c + 1);

        #pragma unroll
        for (int ks = 0; ks < 4; ks++) {
            uint32_t ra[2][4];
            #pragma unroll
            for (int mt = 0; mt < 2; mt++) {
                const int r = wm * 32 + mt * 16 + g;
                ra[mt][0] = *(const uint32_t*)&As[r    ][ks * 16 + tig * 2];
                ra[mt][1] = *(const uint32_t*)&As[r + 8][ks * 16 + tig * 2];
                ra[mt][2] = *(const uint32_t*)&As[r    ][ks * 16 + tig * 2 + 8];
                ra[mt][3] = *(const uint32_t*)&As[r + 8][ks * 16 + tig * 2 + 8];
            }
            #pragma unroll
            for (int nt = 0; nt < 8; nt++) {
                const int rn = wn * 64 + nt * 8 + g;
                uint32_t rb[2];
                rb[0] = *(const uint32_t*)&Bs[rn][ks * 16 + tig * 2];
                rb[1] = *(const uint32_t*)&Bs[rn][ks * 16 + tig * 2 + 8];
                mma16816(acc[0][nt], ra[0], rb);
                mma16816(acc[1][nt], ra[1], rb);
            }
        }
    }

    #pragma unroll
    for (int mt = 0; mt < 2; mt++) {
        const int r = m0 + wm * 32 + mt * 16 + g;
        #pragma unroll
        for (int nt = 0; nt < 8; nt++) {
            const int cc = n0 + wn * 64 + nt * 8 + tig * 2;
            *(float2*)(C + (size_t)r * Ntot + cc)       = make_float2(acc[mt][nt][0], acc[mt][nt][1]);
            *(float2*)(C + (size_t)(r + 8) * Ntot + cc) = make_float2(acc[mt][nt][2], acc[mt][nt][3]);
        }
    }
}

__global__ __launch_bounds__(256) void gemm_qkv_mma() {
    gemm_mma_body<QKVN, DM>(g_aln_hi, g_aln_lo, g_win_hi, g_win_lo, g_qkv);
}
__global__ __launch_bounds__(256) void gemm_out_mma(float* __restrict__ out) {
    gemm_mma_body<DM, DM>(g_att_hi, g_att_lo, g_wo_hi, g_wo_lo, out);
}

// ---------------------------------------------------------------------------
// Parallel GEMM verifies (256 blocks x 128 thr) + scalar fallbacks
// ---------------------------------------------------------------------------
__device__ __forceinline__ float block_dot_reduce(float part) {
    #pragma unroll
    for (int o = 16; o > 0; o >>= 1) part += __shfl_xor_sync(0xffffffffu, part, o);
    __shared__ float sw[4];
    if ((threadIdx.x & 31) == 0) sw[threadIdx.x >> 5] = part;
    __syncthreads();
    return sw[0] + sw[1] + sw[2] + sw[3];
}

__global__ __launch_bounds__(128) void verify_qkv(const float* __restrict__ W) {
    const int i = blockIdx.x;
    const int row = (i * 97 + 31) & (MR - 1);
    const int col = (i * 769 + 7) % QKVN;
    const float* a = g_ln + (size_t)row * DM;
    const float* w = W + (size_t)col * DM;
    float part = 0.f;
    for (int k = threadIdx.x; k < DM; k += 128) part += a[k] * w[k];
    float s = block_dot_reduce(part);
    if (threadIdx.x == 0) {
        const float c = g_qkv[(size_t)row * QKVN + col];
        if (fabsf(c - s) > 0.03f * (fabsf(s) + 1.0f)) g_bad0 = 1;
    }
}
__global__ __launch_bounds__(128) void verify_out(const float* __restrict__ W,
                                                  const float* __restrict__ out) {
    const int i = blockIdx.x;
    const int row = (i * 97 + 31) & (MR - 1);
    const int col = (i * 769 + 7) & (DM - 1);
    const float* a = g_att + (size_t)row * DM;
    const float* w = W + (size_t)col * DM;
    float part = 0.f;
    for (int k = threadIdx.x; k < DM; k += 128) part += a[k] * w[k];
    float s = block_dot_reduce(part);
    if (threadIdx.x == 0) {
        const float c = out[(size_t)row * DM + col];
        if (fabsf(c - s) > 0.03f * (fabsf(s) + 1.0f)) g_bad1 = 1;
    }
}

template <int Mdim, int Ndim, int Kdim>
__device__ __forceinline__ void gemm_body(const float* __restrict__ A,
                                          const float* __restrict__ W,
                                          float* __restrict__ C) {
    __shared__ float As[8][128];
    __shared__ float Bs[8][128];
    const int tid  = threadIdx.x;
    const int tx   = tid & 15;
    const int ty   = tid >> 4;
    const int m0   = blockIdx.y * 128;
    const int n0   = blockIdx.x * 128;
    const int lrow = tid >> 1;
    const int lk   = (tid & 1) * 4;
    float acc[8][8];
    #pragma unroll
    for (int i = 0; i < 8; i++)
        #pragma unroll
        for (int j = 0; j < 8; j++) acc[i][j] = 0.f;
    const float* Aptr = A + (size_t)(m0 + lrow) * Kdim + lk;
    const float* Wptr = W + (size_t)(n0 + lrow) * Kdim + lk;
    for (int k0 = 0; k0 < Kdim; k0 += 8) {
        float4 av = *(const float4*)(Aptr + k0);
        float4 bv = *(const float4*)(Wptr + k0);
        __syncthreads();
        As[lk+0][lrow] = av.x; As[lk+1][lrow] = av.y;
        As[lk+2][lrow] = av.z; As[lk+3][lrow] = av.w;
        Bs[lk+0][lrow] = bv.x; Bs[lk+1][lrow] = bv.y;
        Bs[lk+2][lrow] = bv.z; Bs[lk+3][lrow] = bv.w;
        __syncthreads();
        #pragma unroll
        for (int kk = 0; kk < 8; kk++) {
            float ar[8], br[8];
            #pragma unroll
            for (int i = 0; i < 8; i++) ar[i] = As[kk][ty * 8 + i];
            #pragma unroll
            for (int j = 0; j < 8; j++) br[j] = Bs[kk][tx * 8 + j];
            #pragma unroll
            for (int i = 0; i < 8; i++)
                #pragma unroll
                for (int j = 0; j < 8; j++) acc[i][j] += ar[i] * br[j];
        }
    }
    #pragma unroll
    for (int i = 0; i < 8; i++) {
        float* crow = C + (size_t)(m0 + ty * 8 + i) * Ndim + n0 + tx * 8;
        *(float4*)(crow)     = make_float4(acc[i][0], acc[i][1], acc[i][2], acc[i][3]);
        *(float4*)(crow + 4) = make_float4(acc[i][4], acc[i][5], acc[i][6], acc[i][7]);
    }
}

__global__ __launch_bounds__(256) void fallback_qkv(const float* __restrict__ W) {
    __shared__ int flag;
    if (threadIdx.x == 0) flag = g_bad0;
    __syncthreads();
    if (!flag) return;
    gemm_body<MR, QKVN, DM>(g_ln, W, g_qkv);
}
__global__ __launch_bounds__(256) void fallback_out(const float* __restrict__ W,
                                                    float* __restrict__ out) {
    __shared__ int flag;
    if (threadIdx.x == 0) flag = g_bad1;
    __syncthreads();
    if (!flag) return;
    gemm_body<MR, DM, DM>(g_att, W, out);
}

// ---------------------------------------------------------------------------
// RoPE (R12-proven)
// ---------------------------------------------------------------------------
__global__ __launch_bounds__(256) void rope_tab_kernel() {
    const int idx = blockIdx.x * 256 + threadIdx.x;
    const int l = idx >> 5, i = idx & 31;
    const double invf = pow(10000.0, -(double)(2 * i) / 64.0);
    double sd, cd;
    sincos((double)l * invf, &sd, &cd);
    g_rope[0][l][i] = (float)cd;
    g_rope[1][l][i] = (float)sd;
}
__global__ __launch_bounds__(256) void rope_apply_kernel() {
    const int idx = blockIdx.x * 256 + threadIdx.x;
    const int i = idx & 31;
    const int h = (idx >> 5) & 15;
    const int l = (idx >> 9) & 2047;
    const int b = idx >> 20;
    const float cs = g_rope[0][l][i];
    const float sn = g_rope[1][l][i];
    const size_t row = (size_t)(b * L_ + l) * QKVN;
    const int cq = h * DK + 2 * i;
    float* q = g_qkv + row + cq;
    float q1 = q[0], q2 = q[1];
    q[0] = q1 * cs - q2 * sn;
    q[1] = q1 * sn + q2 * cs;
    float* k = g_qkv + row + DM + cq;
    float k1 = k[0], k2 = k[1];
    k[0] = k1 * cs - k2 * sn;
    k[1] = k1 * sn + k2 * cs;
}

// ---------------------------------------------------------------------------
// MMA flash attention (FA2-style). 128 thr = 4 warps; 64 queries x one (b,h).
// S = Q.K^T via 3-term bf16 split (validated fragment pattern); P reused as
// A-frags; PV via 3-term split against transposed V tiles. exp on fma pipe.
// ---------------------------------------------------------------------------
__global__ __launch_bounds__(128) void attn_mma() {
    __shared__ unsigned short KsHi[64][72], KsLo[64][72];
    __shared__ unsigned short VtHi[64][72], VtLo[64][72];

    const int bh = blockIdx.y;
    const int b  = bh >> 4;
    const int h  = bh & 15;
    const int q0 = blockIdx.x * 64;
    const int tid  = threadIdx.x;
    const int lane = tid & 31;
    const int warp = tid >> 5;           // 0..3: rows warp*16..+15
    const int g    = lane >> 2;
    const int tig  = lane & 3;

    const int rowg  = q0 + warp * 16 + g;
    const int rowg8 = rowg + 8;
    const size_t bL = (size_t)b * L_;

    // --- preload Q fragments (scale folded, bf16 hi/lo split) ---
    uint32_t qhi[4][4], qlo[4][4];
    {
        const float* qb0 = g_qkv + (bL + rowg)  * QKVN + h * DK;
        const float* qb1 = g_qkv + (bL + rowg8) * QKVN + h * DK;
        #pragma unroll
        for (int kc = 0; kc < 4; kc++) {
            const int c0 = kc * 16 + tig * 2;
            float2 v[4];
            v[0] = *(const float2*)(qb0 + c0);
            v[1] = *(const float2*)(qb1 + c0);
            v[2] = *(const float2*)(qb0 + c0 + 8);
            v[3] = *(const float2*)(qb1 + c0 + 8);
            #pragma unroll
            for (int e = 0; e < 4; e++) {
                float x0 = v[e].x * 0.125f, x1 = v[e].y * 0.125f;
                unsigned short h0 = bfh(x0), h1 = bfh(x1);
                qhi[kc][e] = pack2u(h0, h1);
                qlo[kc][e] = pack2u(bfh(x0 - bff(h0)), bfh(x1 - bff(h1)));
            }
        }
    }

    float of[8][4];
    #pragma unroll
    for (int nt = 0; nt < 8; nt++)
        #pragma unroll
        for (int e = 0; e < 4; e++) of[nt][e] = 0.f;
    float m0 = -1e30f, m1 = -1e30f, l0 = 0.f, l1 = 0.f;

    const float* kbase = g_qkv + bL * QKVN + DM + h * DK;
    const float* vbase = kbase + DM;

    for (int j0 = 0; j0 <= q0; j0 += 64) {
        __syncthreads();
        // --- load K/V tile: fp32 -> bf16 hi/lo; V transposed ---
        {
            const int r    = tid >> 1;
            const int half = (tid & 1) * 32;
            const float* kr = kbase + (size_t)(j0 + r) * QKVN + half;
            const float* vr = vbase + (size_t)(j0 + r) * QKVN + half;
            #pragma unroll
            for (int i4 = 0; i4 < 8; i4++) {
                float4 kv = *(const float4*)(kr + i4 * 4);
                float4 vv = *(const float4*)(vr + i4 * 4);
                const float kf[4] = {kv.x, kv.y, kv.z, kv.w};
                const float vf[4] = {vv.x, vv.y, vv.z, vv.w};
                ushort4 uh, ul;
                unsigned short* ph = &uh.x;
                unsigned short* pl = &ul.x;
                #pragma unroll
                for (int e = 0; e < 4; e++) {
                    unsigned short hh = bfh(kf[e]);
                    ph[e] = hh;
                    pl[e] = bfh(kf[e] - bff(hh));
                }
                *(ushort4*)&KsHi[r][half + i4 * 4] = uh;
                *(ushort4*)&KsLo[r][half + i4 * 4] = ul;
                #pragma unroll
                for (int e = 0; e < 4; e++) {
                    const int d = half + i4 * 4 + e;
                    unsigned short hh = bfh(vf[e]);
                    VtHi[d][r] = hh;
                    VtLo[d][r] = bfh(vf[e] - bff(hh));
                }
            }
        }
        __syncthreads();

        // --- S = Q.K^T (3-term split) ---
        float sf[8][4];
        #pragma unroll
        for (int nt = 0; nt < 8; nt++)
            #pragma unroll
            for (int e = 0; e < 4; e++) sf[nt][e] = 0.f;
        #pragma unroll
        for (int nt = 0; nt < 8; nt++) {
            const int jn = nt * 8 + g;
            #pragma unroll
            for (int kc = 0; kc < 4; kc++) {
                uint32_t bhf[2], blf[2];
                bhf[0] = *(const uint32_t*)&KsHi[jn][kc * 16 + tig * 2];
                bhf[1] = *(const uint32_t*)&KsHi[jn][kc * 16 + tig * 2 + 8];
                blf[0] = *(const uint32_t*)&KsLo[jn][kc * 16 + tig * 2];
                blf[1] = *(const uint32_t*)&KsLo[jn][kc * 16 + tig * 2 + 8];
                mma16816(sf[nt], qhi[kc], bhf);
                mma16816(sf[nt], qlo[kc], bhf);
                mma16816(sf[nt], qhi[kc], blf);
            }
        }

        // --- causal mask (diagonal tile only) ---
        if (j0 == q0) {
            #pragma unroll
            for (int nt = 0; nt < 8; nt++) {
                const int colb = j0 + nt * 8 + tig * 2;
                if (colb     > rowg)  sf[nt][0] = -1e30f;
                if (colb + 1 > rowg)  sf[nt][1] = -1e30f;
                if (colb     > rowg8) sf[nt][2] = -1e30f;
                if (colb + 1 > rowg8) sf[nt][3] = -1e30f;
            }
        }

        // --- online softmax ---
        float mx0 = -1e30f, mx1 = -1e30f;
        #pragma unroll
        for (int nt = 0; nt < 8; nt++) {
            mx0 = fmaxf(mx0, fmaxf(sf[nt][0], sf[nt][1]));
            mx1 = fmaxf(mx1, fmaxf(sf[nt][2], sf[nt][3]));
        }
        mx0 = fmaxf(mx0, __shfl_xor_sync(0xffffffffu, mx0, 1));
        mx0 = fmaxf(mx0, __shfl_xor_sync(0xffffffffu, mx0, 2));
        mx1 = fmaxf(mx1, __shfl_xor_sync(0xffffffffu, mx1, 1));
        mx1 = fmaxf(mx1, __shfl_xor_sync(0xffffffffu, mx1, 2));
        const float nm0 = fmaxf(m0, mx0);
        const float nm1 = fmaxf(m1, mx1);
        const float cr0 = exp2p((m0 - nm0) * LOG2E);
        const float cr1 = exp2p((m1 - nm1) * LOG2E);
        m0 = nm0; m1 = nm1;
        l0 *= cr0; l1 *= cr1;
        #pragma unroll
        for (int nt = 0; nt < 8; nt++) {
            of[nt][0] *= cr0; of[nt][1] *= cr0;
            of[nt][2] *= cr1; of[nt][3] *= cr1;
        }
        float ps0 = 0.f, ps1 = 0.f;
        #pragma unroll
        for (int nt = 0; nt < 8; nt++) {
            sf[nt][0] = exp2p((sf[nt][0] - nm0) * LOG2E);
            sf[nt][1] = exp2p((sf[nt][1] - nm0) * LOG2E);
            sf[nt][2] = exp2p((sf[nt][2] - nm1) * LOG2E);
            sf[nt][3] = exp2p((sf[nt][3] - nm1) * LOG2E);
            ps0 += sf[nt][0] + sf[nt][1];
            ps1 += sf[nt][2] + sf[nt][3];
        }
        l0 += ps0; l1 += ps1;

        // --- PV: P (A-frags from S C-frags, split) x Vt (B-frags, split) ---
        #pragma unroll
        for (int kc = 0; kc < 4; kc++) {
            const float x[8] = {sf[2*kc][0], sf[2*kc][1], sf[2*kc][2], sf[2*kc][3],
                                sf[2*kc+1][0], sf[2*kc+1][1], sf[2*kc+1][2], sf[2*kc+1][3]};
            unsigned short hx[8], lx[8];
            #pragma unroll
            for (int e = 0; e < 8; e++) {
                hx[e] = bfh(x[e]);
                lx[e] = bfh(x[e] - bff(hx[e]));
            }
            uint32_t pah[4], pal[4];
            pah[0] = pack2u(hx[0], hx[1]); pah[1] = pack2u(hx[2], hx[3]);
            pah[2] = pack2u(hx[4], hx[5]); pah[3] = pack2u(hx[6], hx[7]);
            pal[0] = pack2u(lx[0], lx[1]); pal[1] = pack2u(lx[2], lx[3]);
            pal[2] = pack2u(lx[4], lx[5]); pal[3] = pack2u(lx[6], lx[7]);
            #pragma unroll
            for (int nt = 0; nt < 8; nt++) {
                const int dn = nt * 8 + g;
                uint32_t vbh[2], vbl[2];
                vbh[0] = *(const uint32_t*)&VtHi[dn][kc * 16 + tig * 2];
                vbh[1] = *(const uint32_t*)&VtHi[dn][kc * 16 + tig * 2 + 8];
                vbl[0] = *(const uint32_t*)&VtLo[dn][kc * 16 + tig * 2];
                vbl[1] = *(const uint32_t*)&VtLo[dn][kc * 16 + tig * 2 + 8];
                mma16816(of[nt], pah, vbh);
                mma16816(of[nt], pal, vbh);
                mma16816(of[nt], pah, vbl);
            }
        }
    }

    // --- finalize: combine l over tig, normalize, store fp32 + splits ---
    l0 += __shfl_xor_sync(0xffffffffu, l0, 1);
    l0 += __shfl_xor_sync(0xffffffffu, l0, 2);
    l1 += __shfl_xor_sync(0xffffffffu, l1, 1);
    l1 += __shfl_xor_sync(0xffffffffu, l1, 2);
    const float i0 = 1.0f / l0;
    const float i1 = 1.0f / l1;
    const size_t o0 = (bL + rowg)  * DM + h * DK;
    const size_t o1 = (bL + rowg8) * DM + h * DK;
    #pragma unroll
    for (int nt = 0; nt < 8; nt++) {
        const int d0 = nt * 8 + tig * 2;
        float a0 = of[nt][0] * i0, a1 = of[nt][1] * i0;
        float b0 = of[nt][2] * i1, b1 = of[nt][3] * i1;
        *(float2*)(g_att + o0 + d0) = make_float2(a0, a1);
        *(float2*)(g_att + o1 + d0) = make_float2(b0, b1);
        unsigned short h0 = bfh(a0), h1 = bfh(a1);
        *(uint32_t*)((unsigned short*)g_att_hi + o0 + d0) = pack2u(h0, h1);
        *(uint32_t*)((unsigned short*)g_att_lo + o0 + d0) =
            pack2u(bfh(a0 - bff(h0)), bfh(a1 - bff(h1)));
        h0 = bfh(b0); h1 = bfh(b1);
        *(uint32_t*)((unsigned short*)g_att_hi + o1 + d0) = pack2u(h0, h1);
        *(uint32_t*)((unsigned short*)g_att_lo + o1 + d0) =
            pack2u(bfh(b0 - bff(h0)), bfh(b1 - bff(h1)));
    }
}

// ---------------------------------------------------------------------------
// Attention verify: 128 sampled (b,h,q) rows, full reference softmax
// ---------------------------------------------------------------------------
__global__ __launch_bounds__(128) void verify_attn() {
    __shared__ float sc[L_];
    __shared__ float qsh[64];
    __shared__ float red[4];
    __shared__ float red2[2][64];

    const int i = blockIdx.x;
    const int b = i & 3;
    const int h = (i >> 2) & 15;
    const int q = (i * 1021 + 13) & (L_ - 1);
    const int nk = q + 1;
    const int tid = threadIdx.x;
    const size_t bL = (size_t)b * L_;

    if (tid < 64) qsh[tid] = g_qkv[(bL + q) * QKVN + h * DK + tid] * 0.125f;
    __syncthreads();

    float lmax = -1e30f;
    for (int j = tid; j < nk; j += 128) {
        const float* kr = g_qkv + (bL + j) * QKVN + DM + h * DK;
        float s = 0.f;
        for (int d = 0; d < 64; d++) s += qsh[d] * kr[d];
        sc[j] = s;
        lmax = fmaxf(lmax, s);
    }
    #pragma unroll
    for (int o = 16; o > 0; o >>= 1) lmax = fmaxf(lmax, __shfl_xor_sync(0xffffffffu, lmax, o));
    if ((tid & 31) == 0) red[tid >> 5] = lmax;
    __syncthreads();
    const float mx = fmaxf(fmaxf(red[0], red[1]), fmaxf(red[2], red[3]));
    __syncthreads();

    float lpart = 0.f;
    for (int j = tid; j < nk; j += 128) {
        const float e = __expf(sc[j] - mx);
        sc[j] = e;
        lpart += e;
    }
    #pragma unroll
    for (int o = 16; o > 0; o >>= 1) lpart += __shfl_xor_sync(0xffffffffu, lpart, o);
    if ((tid & 31) == 0) red[tid >> 5] = lpart;
    __syncthreads();
    const float lsum = red[0] + red[1] + red[2] + red[3];
    __syncthreads();

    const int d   = tid & 63;
    const int grp = tid >> 6;
    float part = 0.f;
    for (int j = grp; j < nk; j += 2)
        part += sc[j] * g_qkv[(bL + j) * QKVN + 2 * DM + h * DK + d];
    red2[grp][d] = part;
    __syncthreads();
    if (grp == 0) {
        const float oref = (red2[0][d] + red2[1][d]) / lsum;
        const float got  = g_att[(bL + q) * DM + h * DK + d];
        if (fabsf(got - oref) > 2e-3f + 2e-3f * fabsf(oref)) g_bad2 = 1;
    }
}

// ---------------------------------------------------------------------------
// Attention fallback (R12-proven kernel, gated on g_bad2)
// ---------------------------------------------------------------------------
__global__ __launch_bounds__(256, 2) void attn_fallback() {
    __shared__ int flag;
    if (threadIdx.x == 0) flag = g_bad2;
    __syncthreads();
    if (!flag) return;

    __shared__ float ks[64][64];
    __shared__ float vs[64][64];

    const int bh = blockIdx.y;
    const int b  = bh >> 4;
    const int h  = bh & 15;
    const int q0 = blockIdx.x * 128;
    const int tid  = threadIdx.x;
    const int d    = tid & 3;
    const int quad = tid >> 2;
    const int qa = q0 + quad;
    const int qb = q0 + 64 + quad;
    const float scale = 0.125f;

    const float* qpa = g_qkv + (size_t)(b * L_ + qa) * QKVN + h * DK + d * 16;
    const float* qpb = g_qkv + (size_t)(b * L_ + qb) * QKVN + h * DK + d * 16;
    float qra[16], qrb[16];
    #pragma unroll
    for (int c = 0; c < 4; c++) {
        float4 t = *(const float4*)(qpa + c * 4);
        qra[c*4+0] = t.x*scale; qra[c*4+1] = t.y*scale;
        qra[c*4+2] = t.z*scale; qra[c*4+3] = t.w*scale;
        float4 u = *(const float4*)(qpb + c * 4);
        qrb[c*4+0] = u.x*scale; qrb[c*4+1] = u.y*scale;
        qrb[c*4+2] = u.z*scale; qrb[c*4+3] = u.w*scale;
    }

    float oa[16], ob[16];
    #pragma unroll
    for (int i = 0; i < 16; i++) { oa[i] = 0.f; ob[i] = 0.f; }
    float ma = -1e30f, mb = -1e30f, la = 0.f, lb = 0.f;

    const float* kb8 = g_qkv + (size_t)(b * L_) * QKVN + DM + h * DK;
    const float* vb8 = kb8 + DM;

    for (int j0 = 0; j0 < q0 + 128; j0 += 64) {
        __syncthreads();
        for (int t = tid; t < 1024; t += 256) {
            const int r = t >> 4, c4 = t & 15;
            const size_t go = (size_t)(j0 + r) * QKVN + c4 * 4;
            *(float4*)&ks[r][c4 * 4] = *(const float4*)(kb8 + go);
            *(float4*)&vs[r][c4 * 4] = *(const float4*)(vb8 + go);
        }
        __syncthreads();

        for (int jj = 0; jj < 64; jj++) {
            const int j = j0 + jj;
            float sa = 0.f, sbv = 0.f;
            float4 kv[4];
            #pragma unroll
            for (int c = 0; c < 4; c++) kv[c] = *(const float4*)&ks[jj][d * 16 + c * 4];
            #pragma unroll
            for (int c = 0; c < 4; c++) {
                sa  += qra[c*4+0]*kv[c].x + qra[c*4+1]*kv[c].y
                     + qra[c*4+2]*kv[c].z + qra[c*4+3]*kv[c].w;
                sbv += qrb[c*4+0]*kv[c].x + qrb[c*4+1]*kv[c].y
                     + qrb[c*4+2]*kv[c].z + qrb[c*4+3]*kv[c].w;
            }
            sa  += __shfl_xor_sync(0xffffffffu, sa, 1);
            sa  += __shfl_xor_sync(0xffffffffu, sa, 2);
            sbv += __shfl_xor_sync(0xffffffffu, sbv, 1);
            sbv += __shfl_xor_sync(0xffffffffu, sbv, 2);

            if (j <= qb) {
                float4 vv[4];
                #pragma unroll
                for (int c = 0; c < 4; c++) vv[c] = *(const float4*)&vs[jj][d * 16 + c * 4];
                {
                    const float mn = fmaxf(mb, sbv);
                    const float p  = __expf(sbv - mn);
                    if (mn > mb) {
                        const float corr = __expf(mb - mn);
                        lb *= corr;
                        #pragma unroll
                        for (int i = 0; i < 16; i++) ob[i] *= corr;
                        mb = mn;
                    }
                    lb += p;
                    #pragma unroll
                    for (int c = 0; c < 4; c++) {
                        ob[c*4+0] += p * vv[c].x; ob[c*4+1] += p * vv[c].y;
                        ob[c*4+2] += p * vv[c].z; ob[c*4+3] += p * vv[c].w;
                    }
                }
                if (j <= qa) {
                    const float mn = fmaxf(ma, sa);
                    const float p  = __expf(sa - mn);
                    if (mn > ma) {
                        const float corr = __expf(ma - mn);
                        la *= corr;
                        #pragma unroll
                        for (int i = 0; i < 16; i++) oa[i] *= corr;
                        ma = mn;
                    }
                    la += p;
                    #pragma unroll
                    for (int c = 0; c < 4; c++) {
                        oa[c*4+0] += p * vv[c].x; oa[c*4+1] += p * vv[c].y;
                        oa[c*4+2] += p * vv[c].z; oa[c*4+3] += p * vv[c].w;
                    }
                }
            }
        }
    }

    const float inva = 1.0f / la;
    const float invb = 1.0f / lb;
    const size_t offa = (size_t)(b * L_ + qa) * DM + h * DK + d * 16;
    const size_t offb = (size_t)(b * L_ + qb) * DM + h * DK + d * 16;
    #pragma unroll
    for (int c = 0; c < 4; c++) {
        float va[4], vb4[4];
        #pragma unroll
        for (int e = 0; e < 4; e++) { va[e] = oa[c*4+e] * inva; vb4[e] = ob[c*4+e] * invb; }
        *(float4*)(g_att + offa + c * 4) = make_float4(va[0], va[1], va[2], va[3]);
        *(float4*)(g_att + offb + c * 4) = make_float4(vb4[0], vb4[1], vb4[2], vb4[3]);
        ushort4 uh, ul;
        unsigned short* ph = &uh.x;
        unsigned short* pl = &ul.x;
        #pragma unroll
        for (int e = 0; e < 4; e++) {
            __nv_bfloat16 hi = __float2bfloat16(va[e]);
            ph[e] = __bfloat16_as_ushort(hi);
            pl[e] = __bfloat16_as_ushort(__float2bfloat16(va[e] - __bfloat162float(hi)));
        }
        *(ushort4*)(g_att_hi + offa + c * 4) = uh;
        *(ushort4*)(g_att_lo + offa + c * 4) = ul;
        #pragma unroll
        for (int e = 0; e < 4; e++) {
            __nv_bfloat16 hi = __float2bfloat16(vb4[e]);
            ph[e] = __bfloat16_as_ushort(hi);
            pl[e] = __bfloat16_as_ushort(__float2bfloat16(vb4[e] - __bfloat162float(hi)));
        }
        *(ushort4*)(g_att_hi + offb + c * 4) = uh;
        *(ushort4*)(g_att_lo + offb + c * 4) = ul;
    }
}

// ---------------------------------------------------------------------------
// launch
// ---------------------------------------------------------------------------
extern "C" void kernel_launch(void* const* d_in, const int* in_sizes, int n_in,
                              void* d_out, int out_size) {
    const float* x    = (const float*)d_in[0];
    const float* W_in = (const float*)d_in[1];
    const float* W_o  = (const float*)d_in[2];
    float* out = (float*)d_out;

    reset_kernel<<<1, 1>>>();
    rope_tab_kernel<<<(L_ * 32) / 256, 256>>>();
    ln_kernel<<<MR, 256>>>(x);
    wsplit_win<<<(QKVN * DM + 255) / 256, 256>>>(W_in);
    wsplit_wo<<<(DM * DM + 255) / 256, 256>>>(W_o);

    dim3 g1(QKVN / 128, MR / 128);
    gemm_qkv_mma<<<g1, 256>>>();
    verify_qkv<<<256, 128>>>(W_in);
    fallback_qkv<<<g1, 256>>>(W_in);

    rope_apply_kernel<<<(B_ * L_ * H_ * 32) / 256, 256>>>();

    dim3 gam(L_ / 64, B_ * H_);
    attn_mma<<<gam, 128>>>();
    verify_attn<<<128, 128>>>();
    dim3 gaf(L_ / 128, B_ * H_);
    attn_fallback<<<gaf, 256>>>();

    dim3 g2(DM / 128, MR / 128);
    gemm_out_mma<<<g2, 256>>>(out);
    verify_out<<<256, 128>>>(W_o, out);
    fallback_out<<<g2, 256>>>(W_o, out);
}